// round 17
// baseline (speedup 1.0000x reference)
#include <cuda_runtime.h>
#include <cuda_fp16.h>
#include <cuda.h>

// DSSIM — fused separable-Gaussian SSIM + mean.
// Round 17: persistent blocks (592) looping over tiles; next tile's TMA
// overlapped with current V-pass; one partial per block. Per-tile math
// identical to round 10 (rel_err 1.389457e-6).

#define IMH 512
#define IMW 512
#define TW 32
#define TH 64
#define SROWS 74
#define STP 48
#define HP 33
#define NT 12288            // 16 x 8 x 96 tiles
#define NPB 592             // persistent blocks (148 SMs x 4)
#define C1F 1.0e-4f
#define C2F 9.0e-4f
#define TMA_BYTES (2 * SROWS * STP * 4)

typedef unsigned long long u64;

static __device__ __forceinline__ u64 pk2(float lo, float hi) {
    u64 r; asm("mov.b64 %0, {%1,%2};" : "=l"(r) : "f"(lo), "f"(hi)); return r;
}
static __device__ __forceinline__ void up2(u64 v, float& lo, float& hi) {
    asm("mov.b64 {%0,%1}, %2;" : "=f"(lo), "=f"(hi) : "l"(v));
}
static __device__ __forceinline__ u64 fma2(u64 a, u64 b, u64 c) {
    u64 d; asm("fma.rn.f32x2 %0, %1, %2, %3;" : "=l"(d) : "l"(a), "l"(b), "l"(c)); return d;
}
static __device__ __forceinline__ u64 add2(u64 a, u64 b) {
    u64 d; asm("add.rn.f32x2 %0, %1, %2;" : "=l"(d) : "l"(a), "l"(b)); return d;
}
static __device__ __forceinline__ unsigned smem32(const void* p) {
    unsigned a; asm("{ .reg .u64 t; cvta.to.shared.u64 t, %1; cvt.u32.u64 %0, t; }" : "=r"(a) : "l"(p));
    return a;
}
static __device__ __forceinline__ void mwait(unsigned mb, unsigned phase) {
    unsigned done;
    asm volatile("{\n\t.reg .pred p;\n\t"
                 "mbarrier.try_wait.parity.acquire.cta.shared::cta.b64 p, [%1], %2;\n\t"
                 "selp.b32 %0, 1, 0, p;\n\t}"
                 : "=r"(done) : "r"(mb), "r"(phase) : "memory");
    if (!done) {
        asm volatile("{\n\t.reg .pred P1;\n\tW0_%=:\n\t"
                     "mbarrier.try_wait.parity.acquire.cta.shared::cta.b64 P1, [%0], %1, 0x989680;\n\t"
                     "@P1 bra.uni W1_%=;\n\tbra.uni W0_%=;\n\tW1_%=:\n\t}"
                     :: "r"(mb), "r"(phase) : "memory");
    }
}

struct __align__(8) H2x2 { __half2 a, b; };

__device__ float g_part[NPB];

#define ACCS(kk, va, vb) do {                                           \
    const float _s  = fmaf((va), (va), (vb) * (vb));                    \
    const float _xy = (va) * (vb);                                      \
    const u64 _A = pk2((va), (vb));                                     \
    const u64 _B = pk2(_s, _xy);                                        \
    _Pragma("unroll")                                                   \
    for (int j = 0; j < 8; ++j) {                                       \
        const int t = (kk) - j;                                         \
        if (t >= 0 && t <= 10) {                                        \
            const int wi = (t < 6) ? t : 10 - t;                        \
            aA[j] = fma2(ww[wi], _A, aA[j]);                            \
            aB[j] = fma2(ww[wi], _B, aB[j]);                            \
        }                                                               \
    }                                                                   \
} while (0)

// Issue TMA pair for tile T (plane = T>>7, ty = (T&127)>>4, tx = T&15)
#define ISSUE_TMA(T) do {                                                       \
    const int _pl = (T) >> 7;                                                   \
    const int _rm = (T) & 127;                                                  \
    const int _cy = ((_rm >> 4) << 6) - 5;                                      \
    const int _cx = ((_rm & 15) << 5) - 8;                                      \
    asm volatile("mbarrier.arrive.expect_tx.shared.b64 _, [%0], %1;"            \
                 :: "r"(mb), "r"((unsigned)TMA_BYTES) : "memory");              \
    asm volatile("cp.async.bulk.tensor.3d.shared::cta.global.tile.mbarrier::complete_tx::bytes " \
                 "[%0], [%1, {%2, %3, %4}], [%5];"                              \
                 :: "r"(smem32(sT1)), "l"(&tm1), "r"(_cx), "r"(_cy), "r"(_pl), "r"(mb) : "memory"); \
    asm volatile("cp.async.bulk.tensor.3d.shared::cta.global.tile.mbarrier::complete_tx::bytes " \
                 "[%0], [%1, {%2, %3, %4}], [%5];"                              \
                 :: "r"(smem32(sT2)), "l"(&tm2), "r"(_cx), "r"(_cy), "r"(_pl), "r"(mb) : "memory"); \
} while (0)

__global__ __launch_bounds__(256, 4) void dssim_pers(
    const __grid_constant__ CUtensorMap tm1,
    const __grid_constant__ CUtensorMap tm2,
    const float* __restrict__ kern)
{
    __shared__ alignas(128) float sT1[SROWS * STP];
    __shared__ alignas(128) float sT2[SROWS * STP];
    __shared__ alignas(16)  H2x2  sH[SROWS * HP];
    __shared__ alignas(8)   u64   mbar;
    __shared__ float sW[6];
    __shared__ float sWarp[8];

    const int tid = threadIdx.x;
    const int b   = blockIdx.x;
    const unsigned mb = smem32(&mbar);

    if (tid == 0) {
        asm volatile("mbarrier.init.shared.b64 [%0], 1;" :: "r"(mb) : "memory");
        asm volatile("fence.proxy.async.shared::cta;" ::: "memory");
        ISSUE_TMA(b);                     // first tile's load in flight
    }
    if (tid < 6) {
        float s = 0.f;
        #pragma unroll
        for (int j = 0; j < 11; ++j) s += kern[tid * 11 + j];
        sW[tid] = s;
    }
    __syncthreads();

    u64 ww[6];
    #pragma unroll
    for (int i = 0; i < 6; ++i) { float w = sW[i]; ww[i] = pk2(w, w); }
    const u64 NEGH = pk2(-0.5f, -0.5f);
    __half2 wh[6];
    #pragma unroll
    for (int i = 0; i < 6; ++i) wh[i] = __float2half2_rn(sW[i]);

    const int x  = tid & 31;
    const int ys = (tid >> 5) << 3;
    float acc = 0.f;
    unsigned it = 0;

    #pragma unroll 1
    for (int T = b; T < NT; T += NPB, ++it) {
        mwait(mb, it & 1u);

        // ---- H-pass: 296 tasks on 256 threads ----
        #pragma unroll 1
        for (int g = tid; g < SROWS * 4; g += 256) {
            const int r  = g >> 2;
            const int cx = (g & 3) << 3;
            u64 aA[8], aB[8];
            #pragma unroll
            for (int j = 0; j < 8; ++j) { aA[j] = 0ull; aB[j] = 0ull; }
            const float4* r1 = (const float4*)&sT1[r * STP];
            const float4* r2 = (const float4*)&sT2[r * STP];
            const int qb = cx >> 2;
            #pragma unroll
            for (int qi = 0; qi < 6; ++qi) {
                const float4 A4 = r1[qb + qi];
                const float4 B4 = r2[qb + qi];
                u64 pa, pb; float a0,a1,b0,b1,a2,a3,b2,b3;
                pa = add2(pk2(A4.x, A4.y), NEGH); up2(pa, a0, a1);
                pb = add2(pk2(B4.x, B4.y), NEGH); up2(pb, b0, b1);
                { const int k = 4 * qi - 3;
                  if (k >= 0 && k <= 17) ACCS(k, a0, b0);
                  if (k + 1 >= 0 && k + 1 <= 17) ACCS(k + 1, a1, b1); }
                pa = add2(pk2(A4.z, A4.w), NEGH); up2(pa, a2, a3);
                pb = add2(pk2(B4.z, B4.w), NEGH); up2(pb, b2, b3);
                { const int k = 4 * qi - 1;
                  if (k >= 0 && k <= 17) ACCS(k, a2, b2);
                  if (k + 1 <= 17) ACCS(k + 1, a3, b3); }
            }
            #pragma unroll
            for (int j = 0; j < 8; ++j) {
                float m1, m2, s, xy;
                up2(aA[j], m1, m2);
                up2(aB[j], s, xy);
                H2x2 h;
                h.a = __floats2half2_rn(m1, m2);
                h.b = __floats2half2_rn(s, xy);
                sH[r * HP + cx + j] = h;
            }
        }
        __syncthreads();                       // sT consumed, sH complete

        if (tid == 0 && T + NPB < NT) {        // overlap next load with V-pass
            asm volatile("fence.proxy.async.shared::cta;" ::: "memory");
            ISSUE_TMA(T + NPB);
        }

        // ---- V-pass + SSIM ----
        __half2 vA[8], vB[8];
        const __half2 hz = __float2half2_rn(0.f);
        #pragma unroll
        for (int j = 0; j < 8; ++j) { vA[j] = hz; vB[j] = hz; }
        #pragma unroll
        for (int k = 0; k < 18; ++k) {
            const H2x2 h = sH[(ys + k) * HP + x];
            #pragma unroll
            for (int j = 0; j < 8; ++j) {
                const int t = k - j;
                if (t >= 0 && t <= 10) {
                    const int wi = (t < 6) ? t : 10 - t;
                    vA[j] = __hfma2(wh[wi], h.a, vA[j]);
                    vB[j] = __hfma2(wh[wi], h.b, vB[j]);
                }
            }
        }
        #pragma unroll
        for (int j = 0; j < 8; ++j) {
            const float2 m  = __half22float2(vA[j]);
            const float2 sx = __half22float2(vB[j]);
            const float t2 = m.x + m.y;
            const float p  = m.x * m.y;
            const float q2 = fmaf(m.x, m.x, m.y * m.y);
            const float mu12 = fmaf(0.5f, t2, p + 0.25f);
            const float A2   = q2 + t2 + 0.5f;
            const float num = fmaf(2.f, mu12, C1F) * fmaf(2.f, sx.y - p, C2F);
            const float den = (A2 + C1F) * ((sx.x - q2) + C2F);
            acc += (1.f - __fdividef(num, den)) * 0.5f;
        }
        __syncthreads();                       // sH reads done before next H-pass
    }

    // ---- one partial per block ----
    #pragma unroll
    for (int o = 16; o; o >>= 1) acc += __shfl_xor_sync(0xffffffffu, acc, o);
    if ((tid & 31) == 0) sWarp[tid >> 5] = acc;
    __syncthreads();
    if (tid == 0) {
        float bs = 0.f;
        #pragma unroll
        for (int i = 0; i < 8; ++i) bs += sWarp[i];
        g_part[b] = bs;
    }
}

// Persistent naive fallback (tensormap-encode failure only)
__global__ __launch_bounds__(256) void dssim_naive(
    const float* __restrict__ im1, const float* __restrict__ im2, const float* __restrict__ kern)
{
    __shared__ float sK[121], sWarp[8];
    const int tid = threadIdx.x;
    const int b = blockIdx.x;
    if (tid < 121) sK[tid] = kern[tid];
    __syncthreads();
    float acc = 0.f;
    for (int T = b; T < NT; T += NPB) {
        const int pl = T >> 7, rm = T & 127;
        const int y0 = (rm >> 4) << 6, x0 = (rm & 15) << 5;
        const size_t pb = (size_t)pl * IMH * IMW;
        const int x = x0 + (tid & 31);
        const int yb = y0 + ((tid >> 5) << 3);
        for (int py = 0; py < 8; ++py) {
            const int y = yb + py;
            float m1 = 0, m2 = 0, xx = 0, yy = 0, xy = 0;
            for (int t = 0; t < 121; ++t) {
                const int gy = y + t / 11 - 5, gx = x + t % 11 - 5;
                float a = 0, c = 0;
                if ((unsigned)gy < IMH && (unsigned)gx < IMW) {
                    a = im1[pb + (size_t)gy * IMW + gx]; c = im2[pb + (size_t)gy * IMW + gx];
                }
                const float w = sK[t];
                m1 += w * a; m2 += w * c; xx += w * a * a; yy += w * c * c; xy += w * a * c;
            }
            const float mu12 = m1 * m2, A2 = m1 * m1 + m2 * m2;
            const float num = (2.f * mu12 + C1F) * (2.f * (xy - mu12) + C2F);
            const float den = (A2 + C1F) * ((xx + yy - A2) + C2F);
            acc += (1.f - num / den) * 0.5f;
        }
    }
    #pragma unroll
    for (int o = 16; o; o >>= 1) acc += __shfl_xor_sync(0xffffffffu, acc, o);
    if ((tid & 31) == 0) sWarp[tid >> 5] = acc;
    __syncthreads();
    if (tid == 0) {
        float bs = 0.f;
        #pragma unroll
        for (int i = 0; i < 8; ++i) bs += sWarp[i];
        g_part[b] = bs;
    }
}

// Final reduce: 592 partials, fixed order, fp64, deterministic.
__global__ __launch_bounds__(256) void dssim_reduce(float* __restrict__ out)
{
    __shared__ double sd[256];
    const int t = threadIdx.x;
    double s = 0.0;
    #pragma unroll
    for (int i = 0; i < 3; ++i) {
        const int idx = t + (i << 8);
        if (idx < NPB) s += (double)g_part[idx];
    }
    sd[t] = s;
    __syncthreads();
    #pragma unroll
    for (int o = 128; o; o >>= 1) { if (t < o) sd[t] += sd[t + o]; __syncthreads(); }
    if (t == 0) out[0] = (float)(sd[0] / (double)(32.0 * 3.0 * 512.0 * 512.0));
}

typedef CUresult (*PFN_enc)(CUtensorMap*, CUtensorMapDataType, cuuint32_t, void*,
    const cuuint64_t*, const cuuint64_t*, const cuuint32_t*, const cuuint32_t*,
    CUtensorMapInterleave, CUtensorMapSwizzle, CUtensorMapL2promotion, CUtensorMapFloatOOBfill);

static bool build_tmap(PFN_enc enc, CUtensorMap* tm, const void* ptr)
{
    cuuint64_t dims[3] = {IMW, IMH, 96};
    cuuint64_t str[2] = {IMW * 4ull, (cuuint64_t)IMH * IMW * 4ull};
    cuuint32_t box[3] = {STP, SROWS, 1};
    cuuint32_t es[3] = {1, 1, 1};
    return enc(tm, CU_TENSOR_MAP_DATA_TYPE_FLOAT32, 3, (void*)ptr, dims, str, box, es,
               CU_TENSOR_MAP_INTERLEAVE_NONE, CU_TENSOR_MAP_SWIZZLE_NONE,
               CU_TENSOR_MAP_L2_PROMOTION_L2_128B, CU_TENSOR_MAP_FLOAT_OOB_FILL_NONE) == CUDA_SUCCESS;
}

extern "C" void kernel_launch(void* const* d_in, const int* in_sizes, int n_in,
                              void* d_out, int out_size)
{
    const float* im1 = (const float*)d_in[0];
    const float* im2 = (const float*)d_in[1];
    const float* kern = (const float*)d_in[2];
    float* out = (float*)d_out;

    PFN_enc enc = nullptr;
    {
        void* fp = nullptr;
        cudaDriverEntryPointQueryResult st = cudaDriverEntryPointSymbolNotFound;
        if (cudaGetDriverEntryPoint("cuTensorMapEncodeTiled", &fp, cudaEnableDefault, &st) == cudaSuccess &&
            st == cudaDriverEntryPointSuccess)
            enc = (PFN_enc)fp;
    }
    CUtensorMap tm1, tm2;
    if (enc && build_tmap(enc, &tm1, im1) && build_tmap(enc, &tm2, im2))
        dssim_pers<<<NPB, 256>>>(tm1, tm2, kern);
    else
        dssim_naive<<<NPB, 256>>>(im1, im2, kern);

    dssim_reduce<<<1, 256>>>(out);
}